// round 16
// baseline (speedup 1.0000x reference)
#include <cuda_runtime.h>
#include <cuda_fp16.h>
#include <cstdint>

#define NB  2
#define SEQ 1024
#define DIM 1024
#define NH  16
#define DK  64
#define FF  4096
#define NL  4
#define MROWS (NB*SEQ)
#define QKVW 3072

// ---------------- PTX helpers ------------------------------------------------
__device__ __forceinline__ uint32_t smem_to_u32(const void* p) {
    uint32_t a;
    asm("{ .reg .u64 t; cvta.to.shared.u64 t, %1; cvt.u32.u64 %0, t; }" : "=r"(a) : "l"(p));
    return a;
}
__device__ __forceinline__ void cpasync16(uint32_t dst, const void* src) {
    asm volatile("cp.async.cg.shared.global [%0], [%1], 16;"
                 :: "r"(dst), "l"(__cvta_generic_to_global(src)) : "memory");
}
__device__ __forceinline__ void cpcommit() { asm volatile("cp.async.commit_group;" ::: "memory"); }
__device__ __forceinline__ void cpwait0()  { asm volatile("cp.async.wait_group 0;" ::: "memory"); }
__device__ __forceinline__ void cpwait1()  { asm volatile("cp.async.wait_group 1;" ::: "memory"); }
__device__ __forceinline__ void ldsm4(uint32_t& r0, uint32_t& r1, uint32_t& r2, uint32_t& r3, uint32_t a) {
    asm volatile("ldmatrix.sync.aligned.m8n8.x4.shared.b16 {%0,%1,%2,%3}, [%4];"
                 : "=r"(r0), "=r"(r1), "=r"(r2), "=r"(r3) : "r"(a));
}
__device__ __forceinline__ void ldsm2(uint32_t& r0, uint32_t& r1, uint32_t a) {
    asm volatile("ldmatrix.sync.aligned.m8n8.x2.shared.b16 {%0,%1}, [%2];"
                 : "=r"(r0), "=r"(r1) : "r"(a));
}
__device__ __forceinline__ void ldsm4t(uint32_t& r0, uint32_t& r1, uint32_t& r2, uint32_t& r3, uint32_t a) {
    asm volatile("ldmatrix.sync.aligned.m8n8.x4.trans.shared.b16 {%0,%1,%2,%3}, [%4];"
                 : "=r"(r0), "=r"(r1), "=r"(r2), "=r"(r3) : "r"(a));
}
__device__ __forceinline__ void mmaF(float* d, const uint32_t* a, const uint32_t* b) {
    asm volatile("mma.sync.aligned.m16n8k16.row.col.f32.f16.f16.f32 "
                 "{%0,%1,%2,%3}, {%4,%5,%6,%7}, {%8,%9}, {%0,%1,%2,%3};"
                 : "+f"(d[0]), "+f"(d[1]), "+f"(d[2]), "+f"(d[3])
                 : "r"(a[0]), "r"(a[1]), "r"(a[2]), "r"(a[3]), "r"(b[0]), "r"(b[1]));
}
__device__ __forceinline__ uint32_t packh(float a, float b) {
    __half2 h = __floats2half2_rn(a, b);
    return *(uint32_t*)&h;
}

// ---------------- scratch -----------------------------------------------------
__device__ float  g_Pf [MROWS*DIM];     // pre-BN fp32 scratch
__device__ float  g_Xf [MROWS*DIM];     // fp32 residual: block input (post-bn3)
__device__ float  g_X1f[MROWS*DIM];     // fp32 residual: post-bn1
__device__ __half g_Xh  [MROWS*DIM];
__device__ __half g_X1h [MROWS*DIM];
__device__ __half g_Yh  [MROWS*DIM];
__device__ __half g_QKVh[MROWS*QKVW];
__device__ __half g_Oh  [MROWS*DIM];
__device__ __half g_Hh  [MROWS*FF];
__device__ __half g_Whi[64u*1024*1024];
__device__ float  g_bQKV1[NL*QKVW], g_bQKV2[NL*QKVW];

#define LAYER_W  (16u*1024*1024)
#define OFF_Q1   (0u)
#define OFF_O1   (3u*1024*1024)
#define OFF_Q2   (4u*1024*1024)
#define OFF_O2   (7u*1024*1024)
#define OFF_W1   (8u*1024*1024)
#define OFF_W2   (12u*1024*1024)

// ---------------- activation round: fp32 -> f16 --------------------------------
__global__ __launch_bounds__(256) void round_f32(const float* __restrict__ x,
        __half* __restrict__ h, int n4)
{
    int i = blockIdx.x * 256 + threadIdx.x;
    if (i >= n4) return;
    float4 v = ((const float4*)x)[i];
    uint2 hp;
    hp.x = packh(v.x, v.y); hp.y = packh(v.z, v.w);
    ((uint2*)h)[i] = hp;
}

// ------------- merged weight transpose+round (single launch, 10 jobs) ----------
struct WJobs {
    const float* W[10];
    int K[10], N[10];
    unsigned long long stride[10];
    unsigned outOff[10];
    int headMode[10];
    int start[10];
};

__global__ __launch_bounds__(256) void wsplit_all(WJobs jobs, __half* __restrict__ oh)
{
    const int bid = blockIdx.x;
    int j = 0;
#pragma unroll
    for (int q = 1; q < 10; q++) if (bid >= jobs.start[q]) j = q;
    const int K = jobs.K[j], N = jobs.N[j];
    const int headMode = jobs.headMode[j];
    const int local = bid - jobs.start[j];
    const int nbk = K >> 5;
    const int perLayer = nbk * (N >> 5);
    const int z = local / perLayer;
    const int rem = local - z * perLayer;
    const int k0 = (rem % nbk) << 5;
    const int n0 = (rem / nbk) << 5;
    const float* Win = jobs.W[j] + (size_t)z * jobs.stride[j];
    const size_t ob = (size_t)z * LAYER_W + jobs.outOff[j];

    __shared__ float t[32][33];
    const int tx = threadIdx.x & 31, ty = threadIdx.x >> 5;
#pragma unroll
    for (int i = 0; i < 4; i++) {
        int k = k0 + ty + 8*i, n = n0 + tx;
        size_t idx = headMode ? ((size_t)(n >> 6) * K * 64 + (size_t)k * 64 + (n & 63))
                              : ((size_t)k * N + n);
        t[ty + 8*i][tx] = Win[idx];
    }
    __syncthreads();
    const int nl = threadIdx.x >> 3;
    const int kq = threadIdx.x & 7;
    const int n = n0 + nl;
    uint2 hp;
    hp.x = packh(t[kq*4 + 0][nl], t[kq*4 + 1][nl]);
    hp.y = packh(t[kq*4 + 2][nl], t[kq*4 + 3][nl]);
    *(uint2*)(oh + ob + (size_t)n * K + k0 + kq*4) = hp;
}

__global__ __launch_bounds__(256) void pack_bias(const float* __restrict__ bq,
        const float* __restrict__ bk, const float* __restrict__ bv, float* __restrict__ out)
{
    int l = blockIdx.y;
    int i = blockIdx.x * 256 + threadIdx.x;
    out[l*QKVW + i]        = bq[l*1024 + i];
    out[l*QKVW + 1024 + i] = bk[l*1024 + i];
    out[l*QKVW + 2048 + i] = bv[l*1024 + i];
}

// ----------- pure-f16 HMMA GEMM (f32 acc): fp32 residual, dual output ----------
#define RSB 144
#define SB_HI 9216
#define STAGE 27648
#define GEMM_SMEM (2*STAGE)   // 55296

__global__ __launch_bounds__(256, 3) void gemm_tc(
        const __half* __restrict__ Ah,
        const __half* __restrict__ Bh,
        const float* __restrict__ bias, const float* __restrict__ R,
        float* __restrict__ C,
        __half* __restrict__ Chi,
        int N, int K, int relu, const int* __restrict__ mskp)
{
    const int m0 = blockIdx.y * 64, n0 = blockIdx.x * 128;
    if (mskp && ((m0 & 1023) >= *mskp) && (n0 >= 1024)) return;  // masked K/V tokens
    extern __shared__ char smem[];
    const uint32_t sb = smem_to_u32(smem);
    const int tid = threadIdx.x, lane = tid & 31, wn = tid >> 5;

    float acc[4][2][4];
#pragma unroll
    for (int i = 0; i < 4; i++)
#pragma unroll
        for (int j = 0; j < 2; j++)
#pragma unroll
            for (int q = 0; q < 4; q++) acc[i][j][q] = 0.f;

    const int nch = K >> 6;
    auto issue = [&](int ch, int stg) {
        const int k0 = ch << 6;
        const uint32_t base = sb + stg * STAGE;
#pragma unroll
        for (int i = tid; i < 1536; i += 256) {
            if (i < 512) {
                int r = i >> 3, c = i & 7;
                cpasync16(base + r * RSB + c * 16,
                          Ah + (size_t)(m0 + r) * K + k0 + c * 8);
            } else {
                int j = i - 512, r = j >> 3, c = j & 7;
                cpasync16(base + SB_HI + r * RSB + c * 16,
                          Bh + (size_t)(n0 + r) * K + k0 + c * 8);
            }
        }
        cpcommit();
    };
    issue(0, 0);

    for (int ch = 0; ch < nch; ch++) {
        cpwait0();
        __syncthreads();
        if (ch + 1 < nch) issue(ch + 1, (ch + 1) & 1);
        const uint32_t stg = sb + (ch & 1) * STAGE;
#pragma unroll
        for (int ks = 0; ks < 4; ks++) {
            uint32_t ah[4][4], bh[2][2];
#pragma unroll
            for (int mt = 0; mt < 4; mt++) {
                uint32_t ad = stg + (mt*16 + (lane & 15)) * RSB + (lane >> 4) * 16 + ks * 32;
                ldsm4(ah[mt][0], ah[mt][1], ah[mt][2], ah[mt][3], ad);
            }
#pragma unroll
            for (int ng = 0; ng < 2; ng++) {
                uint32_t bd = stg + SB_HI + (wn*16 + ng*8 + (lane & 7)) * RSB
                              + ((lane >> 3) & 1) * 16 + ks * 32;
                ldsm2(bh[ng][0], bh[ng][1], bd);
            }
#pragma unroll
            for (int mt = 0; mt < 4; mt++)
#pragma unroll
                for (int ng = 0; ng < 2; ng++)
                    mmaF(acc[mt][ng], ah[mt], bh[ng]);
        }
    }

    const int g = lane >> 2, qc = (lane & 3) * 2;
#pragma unroll
    for (int mt = 0; mt < 4; mt++) {
        const int row0 = m0 + mt*16 + g;
        const int row1 = row0 + 8;
#pragma unroll
        for (int ng = 0; ng < 2; ng++) {
            const int col = n0 + wn*16 + ng*8 + qc;
            const float b0 = bias[col], b1 = bias[col + 1];
            float v00 = acc[mt][ng][0] + b0, v01 = acc[mt][ng][1] + b1;
            float v10 = acc[mt][ng][2] + b0, v11 = acc[mt][ng][3] + b1;
            if (R) {
                float2 r0 = *(const float2*)&R[(size_t)row0 * N + col];
                float2 r1 = *(const float2*)&R[(size_t)row1 * N + col];
                v00 += r0.x; v01 += r0.y; v10 += r1.x; v11 += r1.y;
            }
            if (relu) {
                v00 = fmaxf(v00, 0.f); v01 = fmaxf(v01, 0.f);
                v10 = fmaxf(v10, 0.f); v11 = fmaxf(v11, 0.f);
            }
            if (Chi) {
                *(uint32_t*)&Chi[(size_t)row0 * N + col] = packh(v00, v01);
                *(uint32_t*)&Chi[(size_t)row1 * N + col] = packh(v10, v11);
            } else {
                *(float2*)&C[(size_t)row0 * N + col] = make_float2(v00, v01);
                *(float2*)&C[(size_t)row1 * N + col] = make_float2(v10, v11);
            }
        }
    }
}

// ----------- HMMA flash attention: pure f16 inputs, f32 acc --------------------
#define ARS 144
#define AKV0  18432
#define AKV_STAGE 18432
#define ATT_SMEM (AKV0 + 2*AKV_STAGE)   // 55296

__global__ __launch_bounds__(256, 2) void attn_tc(
        const __half* __restrict__ QKVh,
        __half* __restrict__ Ohi,
        const int* __restrict__ mask_ptr)
{
    extern __shared__ char smem[];
    const uint32_t sb = smem_to_u32(smem);
    const int tid = threadIdx.x, lane = tid & 31, w = tid >> 5;
    const int q0 = blockIdx.x * 128, h = blockIdx.y, b = blockIdx.z;
    const int lim = mask_ptr ? *mask_ptr : SEQ;
    const size_t tokbase = (size_t)b * SEQ;
    const int cq = h * DK, ck = 1024 + h * DK, cv = 2048 + h * DK;

    for (int i = tid; i < 1024; i += 256) {
        int r = i >> 3, c = i & 7;
        cpasync16(sb + r * ARS + c * 16,
                  QKVh + (tokbase + q0 + r) * QKVW + cq + c * 8);
    }
    auto ldkv = [&](int t, int stg) {
        uint32_t base = sb + AKV0 + stg * AKV_STAGE;
        for (int i = tid; i < 512; i += 256) {
            int r = i >> 3, c = i & 7;
            uint32_t off = r * ARS + c * 16;
            size_t row = (tokbase + t * 64 + r) * QKVW;
            cpasync16(base + off,        QKVh + row + ck + c * 8);
            cpasync16(base + 9216 + off, QKVh + row + cv + c * 8);
        }
        cpcommit();
    };
    ldkv(0, 0);

    const int nt = (lim + 63) >> 6;
    const int g = lane >> 2, qc = (lane & 3) * 2;
    const int wq = w * 16;

    float m[2] = {-1e30f, -1e30f}, l[2] = {0.f, 0.f};
    float o[8][4];
#pragma unroll
    for (int i = 0; i < 8; i++)
#pragma unroll
        for (int j = 0; j < 4; j++) o[i][j] = 0.f;

    for (int t = 0; t < nt; t++) {
        __syncthreads();
        if (t + 1 < nt) { ldkv(t + 1, (t + 1) & 1); cpwait1(); }
        else           { cpwait0(); }
        __syncthreads();
        const uint32_t kb = sb + AKV0 + (t & 1) * AKV_STAGE;

        float sc[8][4];
#pragma unroll
        for (int i = 0; i < 8; i++)
#pragma unroll
            for (int j = 0; j < 4; j++) sc[i][j] = 0.f;

#pragma unroll
        for (int ks = 0; ks < 4; ks++) {
            uint32_t qa = sb + (wq + (lane & 15)) * ARS + (lane >> 4) * 16 + ks * 32;
            uint32_t qh[4];
            ldsm4(qh[0], qh[1], qh[2], qh[3], qa);
#pragma unroll
            for (int p = 0; p < 4; p++) {
                uint32_t ka = kb + (p*16 + (lane & 7) + ((lane >> 4) & 1) * 8) * ARS
                              + ((lane >> 3) & 1) * 16 + ks * 32;
                uint32_t kh[4];
                ldsm4(kh[0], kh[1], kh[2], kh[3], ka);
                const uint32_t kh01[2] = {kh[0], kh[1]}, kh23[2] = {kh[2], kh[3]};
                mmaF(sc[2*p],   qh, kh01);
                mmaF(sc[2*p+1], qh, kh23);
            }
        }

        const int t0 = t * 64;
#pragma unroll
        for (int na = 0; na < 8; na++) {
            int c0 = t0 + na*8 + qc, c1 = c0 + 1;
#pragma unroll
            for (int j = 0; j < 2; j++) {
                float s0 = sc[na][2*j]   * 0.125f;
                float s1 = sc[na][2*j+1] * 0.125f;
                sc[na][2*j]   = (c0 < lim) ? s0 : -1e30f;
                sc[na][2*j+1] = (c1 < lim) ? s1 : -1e30f;
            }
        }

#pragma unroll
        for (int j = 0; j < 2; j++) {
            float mx = -1e30f;
#pragma unroll
            for (int na = 0; na < 8; na++)
                mx = fmaxf(mx, fmaxf(sc[na][2*j], sc[na][2*j+1]));
            mx = fmaxf(mx, __shfl_xor_sync(0xffffffffu, mx, 1));
            mx = fmaxf(mx, __shfl_xor_sync(0xffffffffu, mx, 2));
            float mnew = fmaxf(m[j], mx);
            float corr = __expf(m[j] - mnew);
            l[j] *= corr;
            m[j] = mnew;
#pragma unroll
            for (int nd = 0; nd < 8; nd++) { o[nd][2*j] *= corr; o[nd][2*j+1] *= corr; }
            float sum = 0.f;
#pragma unroll
            for (int na = 0; na < 8; na++) {
                float p0 = __expf(sc[na][2*j]   - mnew);
                float p1 = __expf(sc[na][2*j+1] - mnew);
                sc[na][2*j] = p0; sc[na][2*j+1] = p1;
                sum += p0 + p1;
            }
            sum += __shfl_xor_sync(0xffffffffu, sum, 1);
            sum += __shfl_xor_sync(0xffffffffu, sum, 2);
            l[j] += sum;
        }

#pragma unroll
        for (int kp = 0; kp < 4; kp++) {
            uint32_t aph[4] = { packh(sc[2*kp][0],   sc[2*kp][1]),
                                packh(sc[2*kp][2],   sc[2*kp][3]),
                                packh(sc[2*kp+1][0], sc[2*kp+1][1]),
                                packh(sc[2*kp+1][2], sc[2*kp+1][3]) };
#pragma unroll
            for (int vp = 0; vp < 4; vp++) {
                uint32_t va = kb + 9216 + (kp*16 + (lane & 15)) * ARS
                              + (vp*2 + (lane >> 4)) * 16;
                uint32_t vh[4];
                ldsm4t(vh[0], vh[1], vh[2], vh[3], va);
                const uint32_t vh01[2] = {vh[0], vh[1]}, vh23[2] = {vh[2], vh[3]};
                mmaF(o[2*vp],   aph, vh01);
                mmaF(o[2*vp+1], aph, vh23);
            }
        }
    }

#pragma unroll
    for (int j = 0; j < 2; j++) {
        float inv = 1.f / l[j];
        int row = q0 + wq + g + j*8;
        size_t gb = (tokbase + row) * DIM + h * DK;
#pragma unroll
        for (int nd = 0; nd < 8; nd++)
            *(uint32_t*)&Ohi[gb + nd*8 + qc] = packh(o[nd][2*j]*inv, o[nd][2*j+1]*inv);
    }
}

// ------- BatchNorm1d: fp32 in, f16 out + optional fp32 out ---------------------
__global__ __launch_bounds__(256)
void bn_q(const float* __restrict__ P, const float* __restrict__ g,
          const float* __restrict__ be,
          __half* __restrict__ Xh, float* __restrict__ Xf)
{
    const int s = blockIdx.x, tid = threadIdx.x;
    const int lane = tid & 31, w = tid >> 5;
    const size_t r0 = (size_t)s * DIM, r1 = (size_t)(SEQ + s) * DIM;
    float4 v0 = ((const float4*)(P + r0))[tid];
    float4 v1 = ((const float4*)(P + r1))[tid];
    float sum = v0.x+v0.y+v0.z+v0.w + v1.x+v1.y+v1.z+v1.w;
    float sq  = v0.x*v0.x+v0.y*v0.y+v0.z*v0.z+v0.w*v0.w
              + v1.x*v1.x+v1.y*v1.y+v1.z*v1.z+v1.w*v1.w;
#pragma unroll
    for (int off = 16; off; off >>= 1) {
        sum += __shfl_xor_sync(0xffffffffu, sum, off);
        sq  += __shfl_xor_sync(0xffffffffu, sq,  off);
    }
    __shared__ float s1[8], s2[8];
    if (lane == 0) { s1[w] = sum; s2[w] = sq; }
    __syncthreads();
    sum = 0.f; sq = 0.f;
#pragma unroll
    for (int k = 0; k < 8; k++) { sum += s1[k]; sq += s2[k]; }
    const float mean = sum * (1.f/2048.f);
    const float var  = sq  * (1.f/2048.f) - mean*mean;
    const float scl  = g[s] * rsqrtf(var + 1e-5f);
    const float sh   = be[s] - mean * scl;
    v0.x = v0.x*scl + sh; v0.y = v0.y*scl + sh; v0.z = v0.z*scl + sh; v0.w = v0.w*scl + sh;
    v1.x = v1.x*scl + sh; v1.y = v1.y*scl + sh; v1.z = v1.z*scl + sh; v1.w = v1.w*scl + sh;
    uint2 hp;
    hp.x = packh(v0.x, v0.y); hp.y = packh(v0.z, v0.w);
    ((uint2*)(Xh + r0))[tid] = hp;
    hp.x = packh(v1.x, v1.y); hp.y = packh(v1.z, v1.w);
    ((uint2*)(Xh + r1))[tid] = hp;
    if (Xf) {
        ((float4*)(Xf + r0))[tid] = v0;
        ((float4*)(Xf + r1))[tid] = v1;
    }
}

// ---------------- host orchestration -------------------------------------------
extern "C" void kernel_launch(void* const* d_in, const int* in_sizes, int n_in,
                              void* d_out, int out_size)
{
    const float* x   = (const float*)d_in[0];
    const float* Wq1 = (const float*)d_in[1];  const float* bq1 = (const float*)d_in[2];
    const float* Wk1 = (const float*)d_in[3];  const float* bk1 = (const float*)d_in[4];
    const float* Wv1 = (const float*)d_in[5];  const float* bv1 = (const float*)d_in[6];
    const float* Wo1 = (const float*)d_in[7];  const float* bo1 = (const float*)d_in[8];
    const float* Wq2 = (const float*)d_in[9];  const float* bq2 = (const float*)d_in[10];
    const float* Wk2 = (const float*)d_in[11]; const float* bk2 = (const float*)d_in[12];
    const float* Wv2 = (const float*)d_in[13]; const float* bv2 = (const float*)d_in[14];
    const float* Wo2 = (const float*)d_in[15]; const float* bo2 = (const float*)d_in[16];
    const float* g1  = (const float*)d_in[17]; const float* be1 = (const float*)d_in[18];
    const float* g2  = (const float*)d_in[19]; const float* be2 = (const float*)d_in[20];
    const float* g3  = (const float*)d_in[21]; const float* be3 = (const float*)d_in[22];
    const float* W1  = (const float*)d_in[23]; const float* bf1 = (const float*)d_in[24];
    const float* W2  = (const float*)d_in[25]; const float* bf2 = (const float*)d_in[26];
    const int*   msk = (const int*)d_in[27];

    float *Pf, *Xf, *X1f, *bQ1, *bQ2;
    __half *Whi, *Xh, *X1h, *Yh, *QKVh, *Oh, *Hh;
    cudaGetSymbolAddress((void**)&Pf,  g_Pf);
    cudaGetSymbolAddress((void**)&Xf,  g_Xf);
    cudaGetSymbolAddress((void**)&X1f, g_X1f);
    cudaGetSymbolAddress((void**)&Whi, g_Whi);
    cudaGetSymbolAddress((void**)&Xh,  g_Xh);
    cudaGetSymbolAddress((void**)&X1h, g_X1h);
    cudaGetSymbolAddress((void**)&Yh,  g_Yh);
    cudaGetSymbolAddress((void**)&QKVh, g_QKVh);
    cudaGetSymbolAddress((void**)&Oh,  g_Oh);
    cudaGetSymbolAddress((void**)&Hh,  g_Hh);
    cudaGetSymbolAddress((void**)&bQ1, g_bQKV1); cudaGetSymbolAddress((void**)&bQ2, g_bQKV2);

    cudaFuncSetAttribute(gemm_tc, cudaFuncAttributeMaxDynamicSharedMemorySize, GEMM_SMEM);
    cudaFuncSetAttribute(attn_tc, cudaFuncAttributeMaxDynamicSharedMemorySize, ATT_SMEM);

    // ---- merged weight prep (1 launch) + bias concat ----
    {
        const size_t sQ = (size_t)NH * DIM * DK;
        const size_t sO = (size_t)DIM * DIM;
        WJobs jobs;
        const float* Ws[10]  = {Wq1, Wk1, Wv1, Wo1, Wq2, Wk2, Wv2, Wo2, W1, W2};
        const int Ks[10]     = {1024,1024,1024,1024,1024,1024,1024,1024,1024,4096};
        const int Ns[10]     = {1024,1024,1024,1024,1024,1024,1024,1024,4096,1024};
        const unsigned long long st[10] = {sQ,sQ,sQ,sO,sQ,sQ,sQ,sO,(size_t)DIM*FF,(size_t)FF*DIM};
        const unsigned off[10] = {OFF_Q1, OFF_Q1+(1u<<20), OFF_Q1+(2u<<20), OFF_O1,
                                  OFF_Q2, OFF_Q2+(1u<<20), OFF_Q2+(2u<<20), OFF_O2,
                                  OFF_W1, OFF_W2};
        const int hm[10] = {1,1,1,0,1,1,1,0,0,0};
        int cum = 0;
        for (int j = 0; j < 10; j++) {
            jobs.W[j] = Ws[j]; jobs.K[j] = Ks[j]; jobs.N[j] = Ns[j];
            jobs.stride[j] = st[j]; jobs.outOff[j] = off[j]; jobs.headMode[j] = hm[j];
            jobs.start[j] = cum;
            cum += (Ks[j] >> 5) * (Ns[j] >> 5) * NL;
        }
        wsplit_all<<<cum, 256>>>(jobs, Whi);
        pack_bias<<<dim3(4, NL), 256>>>(bq1, bk1, bv1, bQ1);
        pack_bias<<<dim3(4, NL), 256>>>(bq2, bk2, bv2, bQ2);
    }

    const int n4D = MROWS * DIM / 4;
    round_f32<<<n4D/256, 256>>>(x, Xh, n4D);

    dim3 gQKV(QKVW/128, MROWS/64);   // (24,32)
    dim3 gGD(DIM/128,  MROWS/64);    // (8,32)
    dim3 gGF(FF/128,   MROWS/64);    // (32,32)
    dim3 gA(SEQ/128, NH, NB);        // (8,16,2)

    for (int l = 0; l < NL; l++) {
        const __half* WH = Whi + (size_t)l * LAYER_W;
        const size_t dO = (size_t)l * DIM, f1O = (size_t)l * FF;
        const float* Xres = (l == 0) ? x : Xf;            // fp32 block-input residual
        float* bn3out = (l == NL-1) ? (float*)d_out : Xf; // final layer -> d_out

        // masked self-attention (fused QKV; masked K/V tiles skipped)
        gemm_tc<<<gQKV, 256, GEMM_SMEM>>>(Xh, WH+OFF_Q1, bQ1 + l*QKVW,
                nullptr, nullptr, QKVh, QKVW, DIM, 0, msk);
        attn_tc<<<gA, 256, ATT_SMEM>>>(QKVh, Oh, msk);
        gemm_tc<<<gGD, 256, GEMM_SMEM>>>(Oh, WH+OFF_O1, bo1+dO,
                Xres, Pf, nullptr, DIM, DIM, 0, nullptr);
        bn_q<<<SEQ, 256>>>(Pf, g1+dO, be1+dO, X1h, X1f);

        // second (unmasked) attention; residual from block input
        gemm_tc<<<gQKV, 256, GEMM_SMEM>>>(X1h, WH+OFF_Q2, bQ2 + l*QKVW,
                nullptr, nullptr, QKVh, QKVW, DIM, 0, nullptr);
        attn_tc<<<gA, 256, ATT_SMEM>>>(QKVh, Oh, nullptr);
        gemm_tc<<<gGD, 256, GEMM_SMEM>>>(Oh, WH+OFF_O2, bo2+dO,
                Xres, Pf, nullptr, DIM, DIM, 0, nullptr);
        bn_q<<<SEQ, 256>>>(Pf, g2+dO, be2+dO, Yh, nullptr);

        // FFN; residual from X1 (fp32)
        gemm_tc<<<gGF, 256, GEMM_SMEM>>>(Yh, WH+OFF_W1, bf1+f1O,
                nullptr, nullptr, Hh, FF, DIM, 1, nullptr);
        gemm_tc<<<gGD, 256, GEMM_SMEM>>>(Hh, WH+OFF_W2, bf2+dO,
                X1f, Pf, nullptr, DIM, FF, 0, nullptr);
        bn_q<<<SEQ, 256>>>(Pf, g3+dO, be3+dO, Xh, bn3out);
    }
}

// round 17
// speedup vs baseline: 1.0007x; 1.0007x over previous
#include <cuda_runtime.h>
#include <cuda_fp16.h>
#include <cstdint>

#define NB  2
#define SEQ 1024
#define DIM 1024
#define NH  16
#define DK  64
#define FF  4096
#define NL  4
#define MROWS (NB*SEQ)
#define QKVW 3072

// ---------------- PTX helpers ------------------------------------------------
__device__ __forceinline__ uint32_t smem_to_u32(const void* p) {
    uint32_t a;
    asm("{ .reg .u64 t; cvta.to.shared.u64 t, %1; cvt.u32.u64 %0, t; }" : "=r"(a) : "l"(p));
    return a;
}
__device__ __forceinline__ void cpasync16(uint32_t dst, const void* src) {
    asm volatile("cp.async.cg.shared.global [%0], [%1], 16;"
                 :: "r"(dst), "l"(__cvta_generic_to_global(src)) : "memory");
}
__device__ __forceinline__ void cpcommit() { asm volatile("cp.async.commit_group;" ::: "memory"); }
__device__ __forceinline__ void cpwait0()  { asm volatile("cp.async.wait_group 0;" ::: "memory"); }
__device__ __forceinline__ void cpwait1()  { asm volatile("cp.async.wait_group 1;" ::: "memory"); }
__device__ __forceinline__ void ldsm4(uint32_t& r0, uint32_t& r1, uint32_t& r2, uint32_t& r3, uint32_t a) {
    asm volatile("ldmatrix.sync.aligned.m8n8.x4.shared.b16 {%0,%1,%2,%3}, [%4];"
                 : "=r"(r0), "=r"(r1), "=r"(r2), "=r"(r3) : "r"(a));
}
__device__ __forceinline__ void ldsm2(uint32_t& r0, uint32_t& r1, uint32_t a) {
    asm volatile("ldmatrix.sync.aligned.m8n8.x2.shared.b16 {%0,%1}, [%2];"
                 : "=r"(r0), "=r"(r1) : "r"(a));
}
__device__ __forceinline__ void ldsm4t(uint32_t& r0, uint32_t& r1, uint32_t& r2, uint32_t& r3, uint32_t a) {
    asm volatile("ldmatrix.sync.aligned.m8n8.x4.trans.shared.b16 {%0,%1,%2,%3}, [%4];"
                 : "=r"(r0), "=r"(r1), "=r"(r2), "=r"(r3) : "r"(a));
}
__device__ __forceinline__ void mmaF(float* d, const uint32_t* a, const uint32_t* b) {
    asm volatile("mma.sync.aligned.m16n8k16.row.col.f32.f16.f16.f32 "
                 "{%0,%1,%2,%3}, {%4,%5,%6,%7}, {%8,%9}, {%0,%1,%2,%3};"
                 : "+f"(d[0]), "+f"(d[1]), "+f"(d[2]), "+f"(d[3])
                 : "r"(a[0]), "r"(a[1]), "r"(a[2]), "r"(a[3]), "r"(b[0]), "r"(b[1]));
}
__device__ __forceinline__ uint32_t packh(float a, float b) {
    __half2 h = __floats2half2_rn(a, b);
    return *(uint32_t*)&h;
}

// ---------------- scratch -----------------------------------------------------
__device__ float  g_Pf [MROWS*DIM];     // pre-BN fp32 scratch
__device__ float  g_Xf [MROWS*DIM];     // fp32 residual: block input (post-bn3)
__device__ float  g_X1f[MROWS*DIM];     // fp32 residual: post-bn1
__device__ __half g_Xh  [MROWS*DIM];
__device__ __half g_X1h [MROWS*DIM];
__device__ __half g_Yh  [MROWS*DIM];
__device__ __half g_QKVh[MROWS*QKVW];
__device__ __half g_Oh  [MROWS*DIM];
__device__ __half g_Hh  [MROWS*FF];
__device__ __half g_Whi[64u*1024*1024];
__device__ float  g_bQKV1[NL*QKVW], g_bQKV2[NL*QKVW];

#define LAYER_W  (16u*1024*1024)
#define OFF_Q1   (0u)
#define OFF_O1   (3u*1024*1024)
#define OFF_Q2   (4u*1024*1024)
#define OFF_O2   (7u*1024*1024)
#define OFF_W1   (8u*1024*1024)
#define OFF_W2   (12u*1024*1024)

// ---------------- activation round: fp32 -> f16 --------------------------------
__global__ __launch_bounds__(256) void round_f32(const float* __restrict__ x,
        __half* __restrict__ h, int n4)
{
    int i = blockIdx.x * 256 + threadIdx.x;
    if (i >= n4) return;
    float4 v = ((const float4*)x)[i];
    uint2 hp;
    hp.x = packh(v.x, v.y); hp.y = packh(v.z, v.w);
    ((uint2*)h)[i] = hp;
}

// ------ merged weight transpose+round: 64x64 tiles, vectorized (1 launch) ------
struct WJobs {
    const float* W[10];
    int K[10], N[10];
    unsigned long long stride[10];
    unsigned outOff[10];
    int headMode[10];
    int start[10];
};

__global__ __launch_bounds__(256) void wsplit_all(WJobs jobs, __half* __restrict__ oh)
{
    const int bid = blockIdx.x;
    int j = 0;
#pragma unroll
    for (int q = 1; q < 10; q++) if (bid >= jobs.start[q]) j = q;
    const int K = jobs.K[j], N = jobs.N[j];
    const int headMode = jobs.headMode[j];
    const int local = bid - jobs.start[j];
    const int nbk = K >> 6;
    const int perLayer = nbk * (N >> 6);
    const int z = local / perLayer;
    const int rem = local - z * perLayer;
    const int k0 = (rem % nbk) << 6;
    const int n0 = (rem / nbk) << 6;
    const float* Win = jobs.W[j] + (size_t)z * jobs.stride[j];
    const size_t ob = (size_t)z * LAYER_W + jobs.outOff[j];

    // source base: element (kk, nl) at base + kk*rs + nl  (nl contiguous)
    const int rs = headMode ? 64 : N;
    const float* base = Win + (headMode ? ((size_t)(n0 >> 6) * K + k0) * 64
                                        : (size_t)k0 * N + n0);

    __shared__ float t[64][68];          // staged TRANSPOSED: t[nl][kk]
    const int tid = threadIdx.x;
    const int nv = (tid & 15) * 4;       // 4 consecutive n
    const int kr = tid >> 4;             // k row group
#pragma unroll
    for (int i = 0; i < 4; i++) {
        int kk = kr + 16 * i;
        float4 v = *(const float4*)(base + (size_t)kk * rs + nv);
        t[nv + 0][kk] = v.x;
        t[nv + 1][kk] = v.y;
        t[nv + 2][kk] = v.z;
        t[nv + 3][kk] = v.w;
    }
    __syncthreads();

    // pack + store: thread -> (n, quarter q of 16 k values), 2x uint4
    const int n = tid >> 2;
    const int q = tid & 3;
    const float* row = &t[n][q * 16];
    uint4 o0, o1;
    o0.x = packh(row[0],  row[1]);  o0.y = packh(row[2],  row[3]);
    o0.z = packh(row[4],  row[5]);  o0.w = packh(row[6],  row[7]);
    o1.x = packh(row[8],  row[9]);  o1.y = packh(row[10], row[11]);
    o1.z = packh(row[12], row[13]); o1.w = packh(row[14], row[15]);
    __half* dst = oh + ob + (size_t)(n0 + n) * K + k0 + q * 16;
    *(uint4*)dst       = o0;
    *(uint4*)(dst + 8) = o1;
}

__global__ __launch_bounds__(256) void pack_bias(const float* __restrict__ bq,
        const float* __restrict__ bk, const float* __restrict__ bv, float* __restrict__ out)
{
    int l = blockIdx.y;
    int i = blockIdx.x * 256 + threadIdx.x;
    out[l*QKVW + i]        = bq[l*1024 + i];
    out[l*QKVW + 1024 + i] = bk[l*1024 + i];
    out[l*QKVW + 2048 + i] = bv[l*1024 + i];
}

// ----------- pure-f16 HMMA GEMM (f32 acc): fp32 residual, dual output ----------
#define RSB 144
#define SB_HI 9216
#define STAGE 27648
#define GEMM_SMEM (2*STAGE)   // 55296

__global__ __launch_bounds__(256, 3) void gemm_tc(
        const __half* __restrict__ Ah,
        const __half* __restrict__ Bh,
        const float* __restrict__ bias, const float* __restrict__ R,
        float* __restrict__ C,
        __half* __restrict__ Chi,
        int N, int K, int relu, const int* __restrict__ mskp)
{
    const int m0 = blockIdx.y * 64, n0 = blockIdx.x * 128;
    if (mskp && ((m0 & 1023) >= *mskp) && (n0 >= 1024)) return;  // masked K/V tokens
    extern __shared__ char smem[];
    const uint32_t sb = smem_to_u32(smem);
    const int tid = threadIdx.x, lane = tid & 31, wn = tid >> 5;

    float acc[4][2][4];
#pragma unroll
    for (int i = 0; i < 4; i++)
#pragma unroll
        for (int j = 0; j < 2; j++)
#pragma unroll
            for (int q = 0; q < 4; q++) acc[i][j][q] = 0.f;

    const int nch = K >> 6;
    auto issue = [&](int ch, int stg) {
        const int k0 = ch << 6;
        const uint32_t base = sb + stg * STAGE;
#pragma unroll
        for (int i = tid; i < 1536; i += 256) {
            if (i < 512) {
                int r = i >> 3, c = i & 7;
                cpasync16(base + r * RSB + c * 16,
                          Ah + (size_t)(m0 + r) * K + k0 + c * 8);
            } else {
                int j = i - 512, r = j >> 3, c = j & 7;
                cpasync16(base + SB_HI + r * RSB + c * 16,
                          Bh + (size_t)(n0 + r) * K + k0 + c * 8);
            }
        }
        cpcommit();
    };
    issue(0, 0);

    for (int ch = 0; ch < nch; ch++) {
        cpwait0();
        __syncthreads();
        if (ch + 1 < nch) issue(ch + 1, (ch + 1) & 1);
        const uint32_t stg = sb + (ch & 1) * STAGE;
#pragma unroll
        for (int ks = 0; ks < 4; ks++) {
            uint32_t ah[4][4], bh[2][2];
#pragma unroll
            for (int mt = 0; mt < 4; mt++) {
                uint32_t ad = stg + (mt*16 + (lane & 15)) * RSB + (lane >> 4) * 16 + ks * 32;
                ldsm4(ah[mt][0], ah[mt][1], ah[mt][2], ah[mt][3], ad);
            }
#pragma unroll
            for (int ng = 0; ng < 2; ng++) {
                uint32_t bd = stg + SB_HI + (wn*16 + ng*8 + (lane & 7)) * RSB
                              + ((lane >> 3) & 1) * 16 + ks * 32;
                ldsm2(bh[ng][0], bh[ng][1], bd);
            }
#pragma unroll
            for (int mt = 0; mt < 4; mt++)
#pragma unroll
                for (int ng = 0; ng < 2; ng++)
                    mmaF(acc[mt][ng], ah[mt], bh[ng]);
        }
    }

    const int g = lane >> 2, qc = (lane & 3) * 2;
#pragma unroll
    for (int mt = 0; mt < 4; mt++) {
        const int row0 = m0 + mt*16 + g;
        const int row1 = row0 + 8;
#pragma unroll
        for (int ng = 0; ng < 2; ng++) {
            const int col = n0 + wn*16 + ng*8 + qc;
            const float b0 = bias[col], b1 = bias[col + 1];
            float v00 = acc[mt][ng][0] + b0, v01 = acc[mt][ng][1] + b1;
            float v10 = acc[mt][ng][2] + b0, v11 = acc[mt][ng][3] + b1;
            if (R) {
                float2 r0 = *(const float2*)&R[(size_t)row0 * N + col];
                float2 r1 = *(const float2*)&R[(size_t)row1 * N + col];
                v00 += r0.x; v01 += r0.y; v10 += r1.x; v11 += r1.y;
            }
            if (relu) {
                v00 = fmaxf(v00, 0.f); v01 = fmaxf(v01, 0.f);
                v10 = fmaxf(v10, 0.f); v11 = fmaxf(v11, 0.f);
            }
            if (Chi) {
                *(uint32_t*)&Chi[(size_t)row0 * N + col] = packh(v00, v01);
                *(uint32_t*)&Chi[(size_t)row1 * N + col] = packh(v10, v11);
            } else {
                *(float2*)&C[(size_t)row0 * N + col] = make_float2(v00, v01);
                *(float2*)&C[(size_t)row1 * N + col] = make_float2(v10, v11);
            }
        }
    }
}

// ----------- HMMA flash attention: pure f16 inputs, f32 acc --------------------
#define ARS 144
#define AKV0  18432
#define AKV_STAGE 18432
#define ATT_SMEM (AKV0 + 2*AKV_STAGE)   // 55296

__global__ __launch_bounds__(256, 2) void attn_tc(
        const __half* __restrict__ QKVh,
        __half* __restrict__ Ohi,
        const int* __restrict__ mask_ptr)
{
    extern __shared__ char smem[];
    const uint32_t sb = smem_to_u32(smem);
    const int tid = threadIdx.x, lane = tid & 31, w = tid >> 5;
    const int q0 = blockIdx.x * 128, h = blockIdx.y, b = blockIdx.z;
    const int lim = mask_ptr ? *mask_ptr : SEQ;
    const size_t tokbase = (size_t)b * SEQ;
    const int cq = h * DK, ck = 1024 + h * DK, cv = 2048 + h * DK;

    for (int i = tid; i < 1024; i += 256) {
        int r = i >> 3, c = i & 7;
        cpasync16(sb + r * ARS + c * 16,
                  QKVh + (tokbase + q0 + r) * QKVW + cq + c * 8);
    }
    auto ldkv = [&](int t, int stg) {
        uint32_t base = sb + AKV0 + stg * AKV_STAGE;
        for (int i = tid; i < 512; i += 256) {
            int r = i >> 3, c = i & 7;
            uint32_t off = r * ARS + c * 16;
            size_t row = (tokbase + t * 64 + r) * QKVW;
            cpasync16(base + off,        QKVh + row + ck + c * 8);
            cpasync16(base + 9216 + off, QKVh + row + cv + c * 8);
        }
        cpcommit();
    };
    ldkv(0, 0);

    const int nt = (lim + 63) >> 6;
    const int g = lane >> 2, qc = (lane & 3) * 2;
    const int wq = w * 16;

    float m[2] = {-1e30f, -1e30f}, l[2] = {0.f, 0.f};
    float o[8][4];
#pragma unroll
    for (int i = 0; i < 8; i++)
#pragma unroll
        for (int j = 0; j < 4; j++) o[i][j] = 0.f;

    for (int t = 0; t < nt; t++) {
        __syncthreads();
        if (t + 1 < nt) { ldkv(t + 1, (t + 1) & 1); cpwait1(); }
        else           { cpwait0(); }
        __syncthreads();
        const uint32_t kb = sb + AKV0 + (t & 1) * AKV_STAGE;

        float sc[8][4];
#pragma unroll
        for (int i = 0; i < 8; i++)
#pragma unroll
            for (int j = 0; j < 4; j++) sc[i][j] = 0.f;

#pragma unroll
        for (int ks = 0; ks < 4; ks++) {
            uint32_t qa = sb + (wq + (lane & 15)) * ARS + (lane >> 4) * 16 + ks * 32;
            uint32_t qh[4];
            ldsm4(qh[0], qh[1], qh[2], qh[3], qa);
#pragma unroll
            for (int p = 0; p < 4; p++) {
                uint32_t ka = kb + (p*16 + (lane & 7) + ((lane >> 4) & 1) * 8) * ARS
                              + ((lane >> 3) & 1) * 16 + ks * 32;
                uint32_t kh[4];
                ldsm4(kh[0], kh[1], kh[2], kh[3], ka);
                const uint32_t kh01[2] = {kh[0], kh[1]}, kh23[2] = {kh[2], kh[3]};
                mmaF(sc[2*p],   qh, kh01);
                mmaF(sc[2*p+1], qh, kh23);
            }
        }

        const int t0 = t * 64;
#pragma unroll
        for (int na = 0; na < 8; na++) {
            int c0 = t0 + na*8 + qc, c1 = c0 + 1;
#pragma unroll
            for (int j = 0; j < 2; j++) {
                float s0 = sc[na][2*j]   * 0.125f;
                float s1 = sc[na][2*j+1] * 0.125f;
                sc[na][2*j]   = (c0 < lim) ? s0 : -1e30f;
                sc[na][2*j+1] = (c1 < lim) ? s1 : -1e30f;
            }
        }

#pragma unroll
        for (int j = 0; j < 2; j++) {
            float mx = -1e30f;
#pragma unroll
            for (int na = 0; na < 8; na++)
                mx = fmaxf(mx, fmaxf(sc[na][2*j], sc[na][2*j+1]));
            mx = fmaxf(mx, __shfl_xor_sync(0xffffffffu, mx, 1));
            mx = fmaxf(mx, __shfl_xor_sync(0xffffffffu, mx, 2));
            float mnew = fmaxf(m[j], mx);
            float corr = __expf(m[j] - mnew);
            l[j] *= corr;
            m[j] = mnew;
#pragma unroll
            for (int nd = 0; nd < 8; nd++) { o[nd][2*j] *= corr; o[nd][2*j+1] *= corr; }
            float sum = 0.f;
#pragma unroll
            for (int na = 0; na < 8; na++) {
                float p0 = __expf(sc[na][2*j]   - mnew);
                float p1 = __expf(sc[na][2*j+1] - mnew);
                sc[na][2*j] = p0; sc[na][2*j+1] = p1;
                sum += p0 + p1;
            }
            sum += __shfl_xor_sync(0xffffffffu, sum, 1);
            sum += __shfl_xor_sync(0xffffffffu, sum, 2);
            l[j] += sum;
        }

#pragma unroll
        for (int kp = 0; kp < 4; kp++) {
            uint32_t aph[4] = { packh(sc[2*kp][0],   sc[2*kp][1]),
                                packh(sc[2*kp][2],   sc[2*kp][3]),
                                packh(sc[2*kp+1][0], sc[2*kp+1][1]),
                                packh(sc[2*kp+1][2], sc[2*kp+1][3]) };
#pragma unroll
            for (int vp = 0; vp < 4; vp++) {
                uint32_t va = kb + 9216 + (kp*16 + (lane & 15)) * ARS
                              + (vp*2 + (lane >> 4)) * 16;
                uint32_t vh[4];
                ldsm4t(vh[0], vh[1], vh[2], vh[3], va);
                const uint32_t vh01[2] = {vh[0], vh[1]}, vh23[2] = {vh[2], vh[3]};
                mmaF(o[2*vp],   aph, vh01);
                mmaF(o[2*vp+1], aph, vh23);
            }
        }
    }

#pragma unroll
    for (int j = 0; j < 2; j++) {
        float inv = 1.f / l[j];
        int row = q0 + wq + g + j*8;
        size_t gb = (tokbase + row) * DIM + h * DK;
#pragma unroll
        for (int nd = 0; nd < 8; nd++)
            *(uint32_t*)&Ohi[gb + nd*8 + qc] = packh(o[nd][2*j]*inv, o[nd][2*j+1]*inv);
    }
}

// ------- BatchNorm1d: fp32 in, f16 out + optional fp32 out ---------------------
__global__ __launch_bounds__(256)
void bn_q(const float* __restrict__ P, const float* __restrict__ g,
          const float* __restrict__ be,
          __half* __restrict__ Xh, float* __restrict__ Xf)
{
    const int s = blockIdx.x, tid = threadIdx.x;
    const int lane = tid & 31, w = tid >> 5;
    const size_t r0 = (size_t)s * DIM, r1 = (size_t)(SEQ + s) * DIM;
    float4 v0 = ((const float4*)(P + r0))[tid];
    float4 v1 = ((const float4*)(P + r1))[tid];
    float sum = v0.x+v0.y+v0.z+v0.w + v1.x+v1.y+v1.z+v1.w;
    float sq  = v0.x*v0.x+v0.y*v0.y+v0.z*v0.z+v0.w*v0.w
              + v1.x*v1.x+v1.y*v1.y+v1.z*v1.z+v1.w*v1.w;
#pragma unroll
    for (int off = 16; off; off >>= 1) {
        sum += __shfl_xor_sync(0xffffffffu, sum, off);
        sq  += __shfl_xor_sync(0xffffffffu, sq,  off);
    }
    __shared__ float s1[8], s2[8];
    if (lane == 0) { s1[w] = sum; s2[w] = sq; }
    __syncthreads();
    sum = 0.f; sq = 0.f;
#pragma unroll
    for (int k = 0; k < 8; k++) { sum += s1[k]; sq += s2[k]; }
    const float mean = sum * (1.f/2048.f);
    const float var  = sq  * (1.f/2048.f) - mean*mean;
    const float scl  = g[s] * rsqrtf(var + 1e-5f);
    const float sh   = be[s] - mean * scl;
    v0.x = v0.x*scl + sh; v0.y = v0.y*scl + sh; v0.z = v0.z*scl + sh; v0.w = v0.w*scl + sh;
    v1.x = v1.x*scl + sh; v1.y = v1.y*scl + sh; v1.z = v1.z*scl + sh; v1.w = v1.w*scl + sh;
    uint2 hp;
    hp.x = packh(v0.x, v0.y); hp.y = packh(v0.z, v0.w);
    ((uint2*)(Xh + r0))[tid] = hp;
    hp.x = packh(v1.x, v1.y); hp.y = packh(v1.z, v1.w);
    ((uint2*)(Xh + r1))[tid] = hp;
    if (Xf) {
        ((float4*)(Xf + r0))[tid] = v0;
        ((float4*)(Xf + r1))[tid] = v1;
    }
}

// ---------------- host orchestration -------------------------------------------
extern "C" void kernel_launch(void* const* d_in, const int* in_sizes, int n_in,
                              void* d_out, int out_size)
{
    const float* x   = (const float*)d_in[0];
    const float* Wq1 = (const float*)d_in[1];  const float* bq1 = (const float*)d_in[2];
    const float* Wk1 = (const float*)d_in[3];  const float* bk1 = (const float*)d_in[4];
    const float* Wv1 = (const float*)d_in[5];  const float* bv1 = (const float*)d_in[6];
    const float* Wo1 = (const float*)d_in[7];  const float* bo1 = (const float*)d_in[8];
    const float* Wq2 = (const float*)d_in[9];  const float* bq2 = (const float*)d_in[10];
    const float* Wk2 = (const float*)d_in[11]; const float* bk2 = (const float*)d_in[12];
    const float* Wv2 = (const float*)d_in[13]; const float* bv2 = (const float*)d_in[14];
    const float* Wo2 = (const float*)d_in[15]; const float* bo2 = (const float*)d_in[16];
    const float* g1  = (const float*)d_in[17]; const float* be1 = (const float*)d_in[18];
    const float* g2  = (const float*)d_in[19]; const float* be2 = (const float*)d_in[20];
    const float* g3  = (const float*)d_in[21]; const float* be3 = (const float*)d_in[22];
    const float* W1  = (const float*)d_in[23]; const float* bf1 = (const float*)d_in[24];
    const float* W2  = (const float*)d_in[25]; const float* bf2 = (const float*)d_in[26];
    const int*   msk = (const int*)d_in[27];

    float *Pf, *Xf, *X1f, *bQ1, *bQ2;
    __half *Whi, *Xh, *X1h, *Yh, *QKVh, *Oh, *Hh;
    cudaGetSymbolAddress((void**)&Pf,  g_Pf);
    cudaGetSymbolAddress((void**)&Xf,  g_Xf);
    cudaGetSymbolAddress((void**)&X1f, g_X1f);
    cudaGetSymbolAddress((void**)&Whi, g_Whi);
    cudaGetSymbolAddress((void**)&Xh,  g_Xh);
    cudaGetSymbolAddress((void**)&X1h, g_X1h);
    cudaGetSymbolAddress((void**)&Yh,  g_Yh);
    cudaGetSymbolAddress((void**)&QKVh, g_QKVh);
    cudaGetSymbolAddress((void**)&Oh,  g_Oh);
    cudaGetSymbolAddress((void**)&Hh,  g_Hh);
    cudaGetSymbolAddress((void**)&bQ1, g_bQKV1); cudaGetSymbolAddress((void**)&bQ2, g_bQKV2);

    cudaFuncSetAttribute(gemm_tc, cudaFuncAttributeMaxDynamicSharedMemorySize, GEMM_SMEM);
    cudaFuncSetAttribute(attn_tc, cudaFuncAttributeMaxDynamicSharedMemorySize, ATT_SMEM);

    // ---- merged weight prep (1 launch, 64x64 tiles) + bias concat ----
    {
        const size_t sQ = (size_t)NH * DIM * DK;
        const size_t sO = (size_t)DIM * DIM;
        WJobs jobs;
        const float* Ws[10]  = {Wq1, Wk1, Wv1, Wo1, Wq2, Wk2, Wv2, Wo2, W1, W2};
        const int Ks[10]     = {1024,1024,1024,1024,1024,1024,1024,1024,1024,4096};
        const int Ns[10]     = {1024,1024,1024,1024,1024,1024,1024,1024,4096,1024};
        const unsigned long long st[10] = {sQ,sQ,sQ,sO,sQ,sQ,sQ,sO,(size_t)DIM*FF,(size_t)FF*DIM};
        const unsigned off[10] = {OFF_Q1, OFF_Q1+(1u<<20), OFF_Q1+(2u<<20), OFF_O1,
                                  OFF_Q2, OFF_Q2+(1u<<20), OFF_Q2+(2u<<20), OFF_O2,
                                  OFF_W1, OFF_W2};
        const int hm[10] = {1,1,1,0,1,1,1,0,0,0};
        int cum = 0;
        for (int j = 0; j < 10; j++) {
            jobs.W[j] = Ws[j]; jobs.K[j] = Ks[j]; jobs.N[j] = Ns[j];
            jobs.stride[j] = st[j]; jobs.outOff[j] = off[j]; jobs.headMode[j] = hm[j];
            jobs.start[j] = cum;
            cum += (Ks[j] >> 6) * (Ns[j] >> 6) * NL;
        }
        wsplit_all<<<cum, 256>>>(jobs, Whi);   // cum = 16384
        pack_bias<<<dim3(4, NL), 256>>>(bq1, bk1, bv1, bQ1);
        pack_bias<<<dim3(4, NL), 256>>>(bq2, bk2, bv2, bQ2);
    }

    const int n4D = MROWS * DIM / 4;
    round_f32<<<n4D/256, 256>>>(x, Xh, n4D);

    dim3 gQKV(QKVW/128, MROWS/64);   // (24,32)
    dim3 gGD(DIM/128,  MROWS/64);    // (8,32)
    dim3 gGF(FF/128,   MROWS/64);    // (32,32)
    dim3 gA(SEQ/128, NH, NB);        // (8,16,2)

    for (int l = 0; l < NL; l++) {
        const __half* WH = Whi + (size_t)l * LAYER_W;
        const size_t dO = (size_t)l * DIM, f1O = (size_t)l * FF;
        const float* Xres = (l == 0) ? x : Xf;            // fp32 block-input residual
        float* bn3out = (l == NL-1) ? (float*)d_out : Xf; // final layer -> d_out

        // masked self-attention (fused QKV; masked K/V tiles skipped)
        gemm_tc<<<gQKV, 256, GEMM_SMEM>>>(Xh, WH+OFF_Q1, bQ1 + l*QKVW,
                nullptr, nullptr, QKVh, QKVW, DIM, 0, msk);
        attn_tc<<<gA, 256, ATT_SMEM>>>(QKVh, Oh, msk);
        gemm_tc<<<gGD, 256, GEMM_SMEM>>>(Oh, WH+OFF_O1, bo1+dO,
                Xres, Pf, nullptr, DIM, DIM, 0, nullptr);
        bn_q<<<SEQ, 256>>>(Pf, g1+dO, be1+dO, X1h, X1f);

        // second (unmasked) attention; residual from block input
        gemm_tc<<<gQKV, 256, GEMM_SMEM>>>(X1h, WH+OFF_Q2, bQ2 + l*QKVW,
                nullptr, nullptr, QKVh, QKVW, DIM, 0, nullptr);
        attn_tc<<<gA, 256, ATT_SMEM>>>(QKVh, Oh, nullptr);
        gemm_tc<<<gGD, 256, GEMM_SMEM>>>(Oh, WH+OFF_O2, bo2+dO,
                Xres, Pf, nullptr, DIM, DIM, 0, nullptr);
        bn_q<<<SEQ, 256>>>(Pf, g2+dO, be2+dO, Yh, nullptr);

        // FFN; residual from X1 (fp32)
        gemm_tc<<<gGF, 256, GEMM_SMEM>>>(Yh, WH+OFF_W1, bf1+f1O,
                nullptr, nullptr, Hh, FF, DIM, 1, nullptr);
        gemm_tc<<<gGD, 256, GEMM_SMEM>>>(Hh, WH+OFF_W2, bf2+dO,
                X1f, Pf, nullptr, DIM, FF, 0, nullptr);
        bn_q<<<SEQ, 256>>>(Pf, g3+dO, be3+dO, Xh, bn3out);
    }
}